// round 13
// baseline (speedup 1.0000x reference)
#include <cuda_runtime.h>

#define D            64
#define B_SEG        4096
#define THREADS      256
#define NWARP        (THREADS / 32)
#define U1           8            // pass-1 unroll (independent loads/thread)
// Static smem = 4608 B (red 4096 + smean 256 + stg 256). Without the
// MaxDynamicSharedMemorySize opt-in, static + dynamic must fit the default
// 48 KB window: 4608 + 44032 = 48640 <= 49152. Per-CTA ~48.6 KB still caps
// occupancy at 4 CTAs/SM (228 KB SM carveout) -> ~74 MB concurrent
// inter-pass working set, L2-resident.
#define BALLAST      44032

// Segment boundaries: seg[b] = first row index with batch[row] >= b.
__device__ int d_seg[B_SEG + 1];

__global__ void bounds_kernel(const int* __restrict__ batch, int N) {
    int t = blockIdx.x * blockDim.x + threadIdx.x;
    if (t > B_SEG) return;
    int lo = 0, hi = N;
    while (lo < hi) {
        int mid = (lo + hi) >> 1;
        if (__ldg(&batch[mid]) < t) lo = mid + 1; else hi = mid;
    }
    d_seg[t] = lo;
}

__global__ __launch_bounds__(THREADS)
void seg_attn_kernel(const float* __restrict__ x,
                     const float* __restrict__ W,
                     float* __restrict__ out) {
    extern __shared__ float ballast[];   // occupancy limiter (untouched)
    const int b     = blockIdx.x;
    const int start = d_seg[b];
    const int end   = d_seg[b + 1];
    const int n     = end - start;
    const int t     = threadIdx.x;

    __shared__ float red[THREADS * 4];   // 4 KB scratch (reused pass1 / pass2)
    __shared__ float smean[D];
    __shared__ float stg[D];

    // ---- Pass 1: segment sum. 16 lanes/row x 16 row-groups, U1-deep MLP ----
    const float4* __restrict__ x4 = (const float4*)x;
    const int c4 = t & 15;     // float4 column within row
    const int rg = t >> 4;     // row group 0..15
    float4 a[U1];
    #pragma unroll
    for (int u = 0; u < U1; u++) a[u] = make_float4(0.f, 0.f, 0.f, 0.f);

    int r = start + rg;
    for (; r + 16 * (U1 - 1) < end; r += 16 * U1) {
        float4 v[U1];
        #pragma unroll
        for (int u = 0; u < U1; u++)
            v[u] = __ldg(&x4[(long)(r + 16 * u) * 16 + c4]);
        #pragma unroll
        for (int u = 0; u < U1; u++) {
            a[u].x += v[u].x; a[u].y += v[u].y;
            a[u].z += v[u].z; a[u].w += v[u].w;
        }
    }
    for (; r < end; r += 16) {
        float4 v = __ldg(&x4[(long)r * 16 + c4]);
        a[0].x += v.x; a[0].y += v.y; a[0].z += v.z; a[0].w += v.w;
    }
    #pragma unroll
    for (int u = 1; u < U1; u++) {
        a[0].x += a[u].x; a[0].y += a[u].y;
        a[0].z += a[u].z; a[0].w += a[u].w;
    }
    ((float4*)red)[t] = a[0];
    __syncthreads();

    // Reduce 16 row-groups -> mean (64 threads, one column each)
    if (t < D) {
        const int cc4 = t >> 2, cl = t & 3;
        float s = 0.f;
        #pragma unroll
        for (int g = 0; g < 16; g++) s += red[(g * 16 + cc4) * 4 + cl];
        smean[t] = s / (float)max(n, 1);
    }
    __syncthreads();

    // ---- matvec + tanh: tg = tanh(mean @ W)  (W stays L2-hot, 16 KB) ----
    if (t < D) {
        float acc = 0.f;
        #pragma unroll
        for (int k = 0; k < D; k++)
            acc += smean[k] * __ldg(&W[k * D + t]);
        stg[t] = tanhf(acc);
    }
    __syncthreads();

    // ---- Pass 2: coef = sigmoid(x.tg); out += coef*x. 4 rows/warp MLP ----
    const int warp = t >> 5, lane = t & 31;
    const float2 tgl = ((const float2*)stg)[lane];
    const float2* __restrict__ x2 = (const float2*)x;
    float2 acc2 = make_float2(0.f, 0.f);

    const int nMain = n & ~31;           // 8 warps x 4 rows per iteration
    for (int rb = start + warp * 4; rb < start + nMain; rb += 32) {
        float2 v[4];
        #pragma unroll
        for (int j = 0; j < 4; j++)
            v[j] = __ldg(&x2[(long)(rb + j) * 32 + lane]);   // L2-hot re-read
        #pragma unroll
        for (int j = 0; j < 4; j++) {
            float d = v[j].x * tgl.x + v[j].y * tgl.y;
            #pragma unroll
            for (int o = 16; o; o >>= 1) d += __shfl_xor_sync(0xFFFFFFFFu, d, o);
            float coef = 1.f / (1.f + __expf(-d));
            acc2.x += coef * v[j].x;
            acc2.y += coef * v[j].y;
        }
    }
    for (int rr = start + nMain + warp; rr < end; rr += NWARP) {
        float2 v = __ldg(&x2[(long)rr * 32 + lane]);
        float d = v.x * tgl.x + v.y * tgl.y;
        #pragma unroll
        for (int o = 16; o; o >>= 1) d += __shfl_xor_sync(0xFFFFFFFFu, d, o);
        float coef = 1.f / (1.f + __expf(-d));
        acc2.x += coef * v.x;
        acc2.y += coef * v.y;
    }
    __syncthreads();                     // red free for reuse
    ((float2*)red)[warp * 32 + lane] = acc2;
    __syncthreads();

    if (t < 32) {
        float2 s = make_float2(0.f, 0.f);
        #pragma unroll
        for (int g = 0; g < NWARP; g++) {
            float2 v = ((const float2*)red)[g * 32 + t];
            s.x += v.x; s.y += v.y;
        }
        ((float2*)out)[(long)b * 32 + t] = s;   // zeros for empty segments
    }
}

extern "C" void kernel_launch(void* const* d_in, const int* in_sizes, int n_in,
                              void* d_out, int out_size) {
    const float* x     = (const float*)d_in[0];
    const int*   batch = (const int*)d_in[1];
    const float* W     = (const float*)d_in[2];
    float*       out   = (float*)d_out;
    const int N = in_sizes[1];

    bounds_kernel<<<(B_SEG + 1 + 255) / 256, 256>>>(batch, N);
    seg_attn_kernel<<<B_SEG, THREADS, BALLAST>>>(x, W, out);
}